// round 1
// baseline (speedup 1.0000x reference)
#include <cuda_runtime.h>
#include <math.h>

// ---------------- problem constants ----------------
static constexpr int NM  = 8192;
static constexpr int ND  = 6144;
static constexpr int NT  = 14336;      // NM + ND
static constexpr int EMM = 131072;
static constexpr int EDD = 98304;
static constexpr int EG  = 229376;

// ---------------- device scratch (static, allocation-free) ----------------
__device__ float    g_ew[EMM];             // edge weights (mm then dd, reused)
__device__ float    g_dinv[NT];            // deg -> rsqrt(deg)
__device__ float    g_h[NT * 256];         // GEMM out / GAT xl
__device__ float    g_xr[NT * 256];        // GAT xr
__device__ float    g_tmp[NT * 128];       // GCN aggregation buffer
__device__ float    g_x0[NT * 128];
__device__ float    g_x1[NT * 64];
__device__ float    g_x2[NT * 32];
__device__ float    g_logit[(EG + NT) * 4];
__device__ unsigned g_mx[NT * 4];
__device__ float    g_den[NT * 4];
__device__ float    g_agg[NT * 256];
__device__ float    g_cat[NT * 224];

// ---------------- helpers ----------------
__device__ __forceinline__ unsigned f2ord(float f) {
    unsigned b = __float_as_uint(f);
    return (b & 0x80000000u) ? ~b : (b | 0x80000000u);
}
__device__ __forceinline__ float ord2f(unsigned u) {
    return (u & 0x80000000u) ? __uint_as_float(u ^ 0x80000000u)
                             : __uint_as_float(~u);
}

// ---------------- generic small kernels ----------------
__global__ void k_fill(float* p, float v, int n) {
    int i = blockIdx.x * blockDim.x + threadIdx.x;
    if (i < n) p[i] = v;
}
__global__ void k_fillu(unsigned* p, unsigned v, int n) {
    int i = blockIdx.x * blockDim.x + threadIdx.x;
    if (i < n) p[i] = v;
}

// ---------------- GCN ----------------
__global__ void k_gather_ew(const float* __restrict__ mat, const int* __restrict__ src,
                            const int* __restrict__ dst, float* __restrict__ ew,
                            int E, int ncol) {
    int e = blockIdx.x * blockDim.x + threadIdx.x;
    if (e < E) ew[e] = mat[(size_t)src[e] * ncol + dst[e]];
}
__global__ void k_deg_acc(const int* __restrict__ dst, const float* __restrict__ ew,
                          float* __restrict__ deg, int E) {
    int e = blockIdx.x * blockDim.x + threadIdx.x;
    if (e < E) atomicAdd(&deg[dst[e]], ew[e]);
}
__global__ void k_rsqrt(float* p, int n) {
    int i = blockIdx.x * blockDim.x + threadIdx.x;
    if (i < n) p[i] = rsqrtf(p[i]);
}

// Row-tiled GEMM: Y[n,Nout] = act(X[n,K] (opt relu) @ W[K,Nout] + bias)
// blockDim.x == Nout, 8 rows per block; n must be divisible by 8.
__global__ void k_gemm8(const float* __restrict__ X, const float* __restrict__ W,
                        const float* __restrict__ bias, float* __restrict__ Y,
                        int K, int Nout, int in_relu, int out_relu) {
    __shared__ float s[8 * 224];
    int r0 = blockIdx.x * 8;
    for (int idx = threadIdx.x; idx < 8 * K; idx += blockDim.x) {
        int r = idx / K, k = idx - r * K;
        float v = X[(size_t)(r0 + r) * K + k];
        if (in_relu) v = fmaxf(v, 0.f);
        s[r * K + k] = v;
    }
    __syncthreads();
    int j = threadIdx.x;
    float bj = bias ? bias[j] : 0.f;
    float acc[8];
#pragma unroll
    for (int r = 0; r < 8; r++) acc[r] = bj;
    for (int k = 0; k < K; k++) {
        float w = W[(size_t)k * Nout + j];
#pragma unroll
        for (int r = 0; r < 8; r++) acc[r] += s[r * K + k] * w;
    }
#pragma unroll
    for (int r = 0; r < 8; r++) {
        float v = acc[r];
        if (out_relu) v = fmaxf(v, 0.f);
        Y[(size_t)(r0 + r) * Nout + j] = v;
    }
}

// out[i,j] = b[j] + h[i,j]*dinv[i]^2   (self-loop term + bias init)
__global__ void k_gcn_self(const float* __restrict__ h, const float* __restrict__ dinv,
                           const float* __restrict__ b, float* __restrict__ out, int n) {
    int i = blockIdx.x * blockDim.x + threadIdx.x;
    if (i >= n * 128) return;
    int r = i >> 7, j = i & 127;
    float di = dinv[r];
    out[i] = b[j] + h[i] * di * di;
}

// warp-per-edge scatter: out[dst] += h[src] * dinv[src]*w*dinv[dst]
__global__ void k_gcn_edges(const int* __restrict__ src, const int* __restrict__ dst,
                            const float* __restrict__ ew, const float* __restrict__ dinv,
                            const float* __restrict__ h, float* __restrict__ out, int E) {
    int w = (blockIdx.x * blockDim.x + threadIdx.x) >> 5;
    if (w >= E) return;
    int lane = threadIdx.x & 31;
    int s = src[w], d = dst[w];
    float norm = dinv[s] * ew[w] * dinv[d];
    float4 hv = ((const float4*)h)[(size_t)s * 32 + lane];
    float* o = out + (size_t)d * 128 + lane * 4;
    atomicAdd(o + 0, hv.x * norm);
    atomicAdd(o + 1, hv.y * norm);
    atomicAdd(o + 2, hv.z * norm);
    atomicAdd(o + 3, hv.w * norm);
}

__global__ void k_copy_relu(const float* __restrict__ in, float* __restrict__ out, int n) {
    int i = blockIdx.x * blockDim.x + threadIdx.x;
    if (i < n) out[i] = fmaxf(in[i], 0.f);
}

// ---------------- GATv2 ----------------
// warp per edge (edges then self-loops). logits + running max.
__global__ void k_gat_logits(const int* __restrict__ ei, int E, int n,
                             const float* __restrict__ xl, const float* __restrict__ xr,
                             const float* __restrict__ att, unsigned* __restrict__ mx,
                             float* __restrict__ logit, int C) {
    int w = (blockIdx.x * blockDim.x + threadIdx.x) >> 5;
    if (w >= E + n) return;
    int lane = threadIdx.x & 31;
    int s, d;
    if (w < E) { s = ei[w]; d = ei[E + w]; } else { s = d = w - E; }
    int HC = 4 * C;
    const float* xls = xl + (size_t)s * HC;
    const float* xrd = xr + (size_t)d * HC;
#pragma unroll
    for (int h = 0; h < 4; h++) {
        float p = 0.f;
        for (int c = lane; c < C; c += 32) {
            float v = xls[h * C + c] + xrd[h * C + c];
            v = v > 0.f ? v : 0.2f * v;
            p += v * att[h * C + c];
        }
#pragma unroll
        for (int off = 16; off; off >>= 1) p += __shfl_down_sync(0xffffffffu, p, off);
        if (lane == 0) {
            logit[(size_t)w * 4 + h] = p;
            atomicMax(&mx[d * 4 + h], f2ord(p));
        }
    }
}

__global__ void k_gat_exp(const int* __restrict__ ei, int E, int n,
                          const unsigned* __restrict__ mx,
                          float* __restrict__ logit, float* __restrict__ den) {
    int i = blockIdx.x * blockDim.x + threadIdx.x;
    if (i >= (E + n) * 4) return;
    int e = i >> 2, h = i & 3;
    int d = (e < E) ? ei[E + e] : (e - E);
    float ex = expf(logit[i] - ord2f(mx[d * 4 + h]));
    logit[i] = ex;
    atomicAdd(&den[d * 4 + h], ex);
}

__global__ void k_gat_scatter(const int* __restrict__ ei, int E, int n,
                              const float* __restrict__ xl, const float* __restrict__ logit,
                              const float* __restrict__ den, float* __restrict__ agg, int C) {
    int w = (blockIdx.x * blockDim.x + threadIdx.x) >> 5;
    if (w >= E + n) return;
    int lane = threadIdx.x & 31;
    int s, d;
    if (w < E) { s = ei[w]; d = ei[E + w]; } else { s = d = w - E; }
    int HC = 4 * C;
#pragma unroll
    for (int h = 0; h < 4; h++) {
        float alpha = logit[(size_t)w * 4 + h] / den[d * 4 + h];
        for (int c = lane; c < C; c += 32) {
            atomicAdd(&agg[(size_t)d * HC + h * C + c],
                      xl[(size_t)s * HC + h * C + c] * alpha);
        }
    }
}

__global__ void k_gat_final(const float* __restrict__ agg, const float* __restrict__ bias,
                            float* __restrict__ out, int n, int C, int elu) {
    int i = blockIdx.x * blockDim.x + threadIdx.x;
    if (i >= n * C) return;
    int r = i / C, c = i - r * C;
    int HC = 4 * C;
    const float* a = agg + (size_t)r * HC;
    float v = 0.25f * (a[c] + a[C + c] + a[2 * C + c] + a[3 * C + c]) + bias[c];
    if (elu) v = v > 0.f ? v : expm1f(v);
    out[i] = v;
}

__global__ void k_concat(const float* __restrict__ x0, const float* __restrict__ x1,
                         const float* __restrict__ x2, float* __restrict__ cat) {
    int i = blockIdx.x * blockDim.x + threadIdx.x;
    if (i >= NT * 224) return;
    int r = i / 224, j = i - r * 224;
    float v;
    if (j < 128)      v = x0[r * 128 + j];
    else if (j < 192) v = x1[r * 64 + (j - 128)];
    else              v = x2[r * 32 + (j - 192)];
    cat[i] = v;
}

// ---------------- host orchestration ----------------
static inline int cdiv(int a, int b) { return (a + b - 1) / b; }

extern "C" void kernel_launch(void* const* d_in, const int* in_sizes, int n_in,
                              void* d_out, int out_size) {
    const float* mm_f = (const float*)d_in[0];
    const float* d_sf = (const float*)d_in[1];
    const float* ms   = (const float*)d_in[2];
    const float* ds   = (const float*)d_in[3];
    const int*   mme  = (const int*)d_in[4];
    const int*   dde  = (const int*)d_in[5];
    const int*   ei   = (const int*)d_in[6];
    const float* W_m1 = (const float*)d_in[7];
    const float* b_m1 = (const float*)d_in[8];
    const float* W_m2 = (const float*)d_in[9];
    const float* b_m2 = (const float*)d_in[10];
    const float* W_d1 = (const float*)d_in[11];
    const float* b_d1 = (const float*)d_in[12];
    const float* W_d2 = (const float*)d_in[13];
    const float* b_d2 = (const float*)d_in[14];
    const float* Wl1  = (const float*)d_in[15];
    const float* Wr1  = (const float*)d_in[16];
    const float* att1 = (const float*)d_in[17];
    const float* bia1 = (const float*)d_in[18];
    const float* Wl2  = (const float*)d_in[19];
    const float* Wr2  = (const float*)d_in[20];
    const float* att2 = (const float*)d_in[21];
    const float* bia2 = (const float*)d_in[22];
    const float* W_jk = (const float*)d_in[23];
    const float* b_jk = (const float*)d_in[24];

    void *vp;
    float *p_ew, *p_dinv, *p_h, *p_xr, *p_tmp, *p_x0, *p_x1, *p_x2, *p_logit, *p_den, *p_agg, *p_cat;
    unsigned *p_mx;
    cudaGetSymbolAddress(&vp, g_ew);    p_ew    = (float*)vp;
    cudaGetSymbolAddress(&vp, g_dinv);  p_dinv  = (float*)vp;
    cudaGetSymbolAddress(&vp, g_h);     p_h     = (float*)vp;
    cudaGetSymbolAddress(&vp, g_xr);    p_xr    = (float*)vp;
    cudaGetSymbolAddress(&vp, g_tmp);   p_tmp   = (float*)vp;
    cudaGetSymbolAddress(&vp, g_x0);    p_x0    = (float*)vp;
    cudaGetSymbolAddress(&vp, g_x1);    p_x1    = (float*)vp;
    cudaGetSymbolAddress(&vp, g_x2);    p_x2    = (float*)vp;
    cudaGetSymbolAddress(&vp, g_logit); p_logit = (float*)vp;
    cudaGetSymbolAddress(&vp, g_mx);    p_mx    = (unsigned*)vp;
    cudaGetSymbolAddress(&vp, g_den);   p_den   = (float*)vp;
    cudaGetSymbolAddress(&vp, g_agg);   p_agg   = (float*)vp;
    cudaGetSymbolAddress(&vp, g_cat);   p_cat   = (float*)vp;

    // ---- two-layer GCN on one subgraph ----
    auto run_gcn = [&](const float* x, const int* edges, int E, int n, const float* mat,
                       const float* W1, const float* b1, const float* W2, const float* b2,
                       float* out) {
        const int* src = edges;
        const int* dst = edges + E;
        k_gather_ew<<<cdiv(E, 256), 256>>>(mat, src, dst, p_ew, E, n);
        k_fill<<<cdiv(n, 256), 256>>>(p_dinv, 1.f, n);          // self-loop weight
        k_deg_acc<<<cdiv(E, 256), 256>>>(dst, p_ew, p_dinv, E);
        k_rsqrt<<<cdiv(n, 256), 256>>>(p_dinv, n);
        // layer 1: h = x @ W1 ; tmp = b1 + h*dinv^2 ; scatter edges (m1 pre-relu in tmp)
        k_gemm8<<<n / 8, 128>>>(x, W1, nullptr, p_h, 128, 128, 0, 0);
        k_gcn_self<<<cdiv(n * 128, 256), 256>>>(p_h, p_dinv, b1, p_tmp, n);
        k_gcn_edges<<<cdiv(E * 32, 256), 256>>>(src, dst, p_ew, p_dinv, p_h, p_tmp, E);
        // layer 2: h = relu(tmp) @ W2 ; tmp = b2 + h*dinv^2 ; scatter
        k_gemm8<<<n / 8, 128>>>(p_tmp, W2, nullptr, p_h, 128, 128, 1, 0);
        k_gcn_self<<<cdiv(n * 128, 256), 256>>>(p_h, p_dinv, b2, p_tmp, n);
        k_gcn_edges<<<cdiv(E * 32, 256), 256>>>(src, dst, p_ew, p_dinv, p_h, p_tmp, E);
        k_copy_relu<<<cdiv(n * 128, 256), 256>>>(p_tmp, out, n * 128);
    };
    run_gcn(mm_f, mme, EMM, NM, ms, W_m1, b_m1, W_m2, b_m2, p_x0);
    run_gcn(d_sf, dde, EDD, ND, ds, W_d1, b_d1, W_d2, b_d2, p_x0 + (size_t)NM * 128);

    // ---- GATv2 layer ----
    auto run_gat = [&](const float* x, int K, int C, const float* Wl, const float* Wr,
                       const float* att, const float* bias, float* out, int elu) {
        int HC = 4 * C;
        int tot = EG + NT;
        k_gemm8<<<NT / 8, HC>>>(x, Wl, nullptr, p_h,  K, HC, 0, 0);
        k_gemm8<<<NT / 8, HC>>>(x, Wr, nullptr, p_xr, K, HC, 0, 0);
        k_fillu<<<cdiv(NT * 4, 256), 256>>>(p_mx, 0x007FFFFFu, NT * 4);   // f2ord(-inf)
        k_fill<<<cdiv(NT * 4, 256), 256>>>(p_den, 0.f, NT * 4);
        k_fill<<<cdiv(NT * HC, 256), 256>>>(p_agg, 0.f, NT * HC);
        k_gat_logits<<<cdiv(tot * 32, 256), 256>>>(ei, EG, NT, p_h, p_xr, att, p_mx, p_logit, C);
        k_gat_exp<<<cdiv(tot * 4, 256), 256>>>(ei, EG, NT, p_mx, p_logit, p_den);
        k_gat_scatter<<<cdiv(tot * 32, 256), 256>>>(ei, EG, NT, p_h, p_logit, p_den, p_agg, C);
        k_gat_final<<<cdiv(NT * C, 256), 256>>>(p_agg, bias, out, NT, C, elu);
    };
    run_gat(p_x0, 128, 64, Wl1, Wr1, att1, bia1, p_x1, 1);
    run_gat(p_x1, 64,  32, Wl2, Wr2, att2, bia2, p_x2, 0);

    // ---- JumpingKnowledge concat + linear ----
    k_concat<<<cdiv(NT * 224, 256), 256>>>(p_x0, p_x1, p_x2, p_cat);
    k_gemm8<<<NT / 8, 128>>>(p_cat, W_jk, b_jk, (float*)d_out, 224, 128, 0, 0);
}

// round 2
// speedup vs baseline: 1.9339x; 1.9339x over previous
#include <cuda_runtime.h>
#include <math.h>

// ---------------- problem constants ----------------
static constexpr int NM  = 8192;
static constexpr int ND  = 6144;
static constexpr int NT  = 14336;      // NM + ND
static constexpr int EMM = 131072;
static constexpr int EDD = 98304;
static constexpr int EG  = 229376;

// ---------------- device scratch (static, allocation-free) ----------------
__device__ float g_ew[EMM];
__device__ float g_dinv[NT];
__device__ float g_h[NT * 256];        // xl / gemm out
__device__ float g_xr[NT * 256];       // xr
__device__ float g_tmp[NT * 128];      // GCN layer-1 out (pre-relu)
__device__ float g_x0[NT * 128];
__device__ float g_x1[NT * 64];
__device__ float g_x2[NT * 32];
__device__ float g_cat[NT * 224];
// CSR scratch
__device__ int   g_cnt[NT];
__device__ int   g_pos[EG];
__device__ int   g_ptr_mm[NM + 1];
__device__ int   g_src_mm[EMM];
__device__ float g_nrm_mm[EMM];
__device__ int   g_ptr_dd[ND + 1];
__device__ int   g_src_dd[EDD];
__device__ float g_nrm_dd[EDD];
__device__ int   g_ptr_g[NT + 1];
__device__ int   g_src_g[EG];

static inline int cdiv(int a, int b) { return (a + b - 1) / b; }

// ---------------- tiny utility kernels ----------------
__global__ void k_fill(float* p, float v, int n) {
    int i = blockIdx.x * blockDim.x + threadIdx.x;
    if (i < n) p[i] = v;
}
__global__ void k_zeroi(int* p, int n) {
    int i = blockIdx.x * blockDim.x + threadIdx.x;
    if (i < n) p[i] = 0;
}
__global__ void k_rsqrt(float* p, int n) {
    int i = blockIdx.x * blockDim.x + threadIdx.x;
    if (i < n) p[i] = rsqrtf(p[i]);
}

// ---------------- CSR build ----------------
// GCN: gather edge weight from dense matrix + histogram position
__global__ void k_gather_hist(const float* __restrict__ mat, const int* __restrict__ src,
                              const int* __restrict__ dst, float* __restrict__ ew,
                              int* __restrict__ pos, int* __restrict__ cnt,
                              int E, int ncol) {
    int e = blockIdx.x * blockDim.x + threadIdx.x;
    if (e >= E) return;
    ew[e] = mat[(size_t)src[e] * ncol + dst[e]];
    pos[e] = atomicAdd(&cnt[dst[e]], 1);
}
__global__ void k_hist(const int* __restrict__ dst, int* __restrict__ pos,
                       int* __restrict__ cnt, int E) {
    int e = blockIdx.x * blockDim.x + threadIdx.x;
    if (e >= E) return;
    pos[e] = atomicAdd(&cnt[dst[e]], 1);
}
__global__ void k_deg_acc(const int* __restrict__ dst, const float* __restrict__ ew,
                          float* __restrict__ deg, int E) {
    int e = blockIdx.x * blockDim.x + threadIdx.x;
    if (e < E) atomicAdd(&deg[dst[e]], ew[e]);
}
// single-block exclusive scan (n <= 16384), writes rowptr[0..n]
__global__ void k_scan(const int* __restrict__ cnt, int* __restrict__ rowptr, int n) {
    __shared__ int sp[1024];
    int t = threadIdx.x;
    int per = (n + 1023) / 1024;
    int start = t * per;
    int vals[16];
    int local = 0;
    for (int j = 0; j < per; j++) {
        int i = start + j;
        vals[j] = (i < n) ? cnt[i] : 0;
        local += vals[j];
    }
    sp[t] = local;
    __syncthreads();
    for (int off = 1; off < 1024; off <<= 1) {
        int v = (t >= off) ? sp[t - off] : 0;
        __syncthreads();
        sp[t] += v;
        __syncthreads();
    }
    int ex = t ? sp[t - 1] : 0;
    for (int j = 0; j < per; j++) {
        int i = start + j;
        if (i < n) { rowptr[i] = ex; ex += vals[j]; }
    }
    if (t == 1023) rowptr[n] = sp[1023];
}
__global__ void k_scatter_gcn(const int* __restrict__ src, const int* __restrict__ dst,
                              const float* __restrict__ ew, const int* __restrict__ pos,
                              const int* __restrict__ rowptr, const float* __restrict__ dinv,
                              int* __restrict__ csrc, float* __restrict__ cnorm, int E) {
    int e = blockIdx.x * blockDim.x + threadIdx.x;
    if (e >= E) return;
    int d = dst[e], s = src[e];
    int idx = rowptr[d] + pos[e];
    csrc[idx] = s;
    cnorm[idx] = dinv[s] * ew[e] * dinv[d];
}
__global__ void k_scatter_gat(const int* __restrict__ src, const int* __restrict__ dst,
                              const int* __restrict__ pos, const int* __restrict__ rowptr,
                              int* __restrict__ csrc, int E) {
    int e = blockIdx.x * blockDim.x + threadIdx.x;
    if (e >= E) return;
    csrc[rowptr[dst[e]] + pos[e]] = src[e];
}

// ---------------- GEMMs ----------------
// Y[n,Nout] = act(X[n,K]) @ W[K,Nout] (+bias). blockDim.x == Nout, 8 rows/block.
__global__ void k_gemm8(const float* __restrict__ X, const float* __restrict__ W,
                        const float* __restrict__ bias, float* __restrict__ Y,
                        int K, int Nout, int in_relu) {
    __shared__ float s[8 * 224];
    int r0 = blockIdx.x * 8;
    for (int idx = threadIdx.x; idx < 8 * K; idx += blockDim.x) {
        int r = idx / K, k = idx - r * K;
        float v = X[(size_t)(r0 + r) * K + k];
        if (in_relu) v = fmaxf(v, 0.f);
        s[r * K + k] = v;
    }
    __syncthreads();
    int j = threadIdx.x;
    float bj = bias ? bias[j] : 0.f;
    float acc[8];
#pragma unroll
    for (int r = 0; r < 8; r++) acc[r] = bj;
    for (int k = 0; k < K; k++) {
        float w = W[(size_t)k * Nout + j];
#pragma unroll
        for (int r = 0; r < 8; r++) acc[r] += s[r * K + k] * w;
    }
#pragma unroll
    for (int r = 0; r < 8; r++) Y[(size_t)(r0 + r) * Nout + j] = acc[r];
}

// dual GEMM: Yl = X@Wl, Yr = X@Wr (reads X once). blockDim.x == Nout.
__global__ void k_gemm8_dual(const float* __restrict__ X, const float* __restrict__ Wl,
                             const float* __restrict__ Wr, float* __restrict__ Yl,
                             float* __restrict__ Yr, int K, int Nout) {
    __shared__ float s[8 * 128];
    int r0 = blockIdx.x * 8;
    for (int idx = threadIdx.x; idx < 8 * K; idx += blockDim.x) {
        int r = idx / K, k = idx - r * K;
        s[r * K + k] = X[(size_t)(r0 + r) * K + k];
    }
    __syncthreads();
    int j = threadIdx.x;
    float al[8], ar[8];
#pragma unroll
    for (int r = 0; r < 8; r++) { al[r] = 0.f; ar[r] = 0.f; }
    for (int k = 0; k < K; k++) {
        float wl = Wl[(size_t)k * Nout + j];
        float wr = Wr[(size_t)k * Nout + j];
#pragma unroll
        for (int r = 0; r < 8; r++) {
            float x = s[r * K + k];
            al[r] += x * wl;
            ar[r] += x * wr;
        }
    }
#pragma unroll
    for (int r = 0; r < 8; r++) {
        Yl[(size_t)(r0 + r) * Nout + j] = al[r];
        Yr[(size_t)(r0 + r) * Nout + j] = ar[r];
    }
}

// ---------------- GCN aggregation (warp per dst node, CSR gather) ----------------
__global__ void k_gcn_agg(const int* __restrict__ rowptr, const int* __restrict__ csrc,
                          const float* __restrict__ cnorm, const float* __restrict__ h,
                          const float* __restrict__ dinv, const float* __restrict__ b,
                          float* __restrict__ out, int n, int out_relu) {
    int w = (blockIdx.x * blockDim.x + threadIdx.x) >> 5;
    if (w >= n) return;
    int lane = threadIdx.x & 31;
    float di = dinv[w];
    float4 self = ((const float4*)h)[(size_t)w * 32 + lane];
    float4 bb = ((const float4*)b)[lane];
    float sc = di * di;
    float4 acc;
    acc.x = bb.x + self.x * sc;
    acc.y = bb.y + self.y * sc;
    acc.z = bb.z + self.z * sc;
    acc.w = bb.w + self.w * sc;
    int e1 = rowptr[w + 1];
    for (int e = rowptr[w]; e < e1; e++) {
        int s = csrc[e];
        float nm = cnorm[e];
        float4 hv = ((const float4*)h)[(size_t)s * 32 + lane];
        acc.x += hv.x * nm;
        acc.y += hv.y * nm;
        acc.z += hv.z * nm;
        acc.w += hv.w * nm;
    }
    if (out_relu) {
        acc.x = fmaxf(acc.x, 0.f); acc.y = fmaxf(acc.y, 0.f);
        acc.z = fmaxf(acc.z, 0.f); acc.w = fmaxf(acc.w, 0.f);
    }
    ((float4*)out)[(size_t)w * 32 + lane] = acc;
}

// ---------------- fused GATv2 (warp per dst node, online softmax) ----------------
// Layout: 8 lanes per head (head = lane>>3), lane handles c = (lane&7) + 8*i.
template <int C>
__global__ void k_gat_fused(const int* __restrict__ rowptr, const int* __restrict__ csrc,
                            const float* __restrict__ xl, const float* __restrict__ xr,
                            const float* __restrict__ att, const float* __restrict__ bias,
                            float* __restrict__ out, int n, int elu) {
    constexpr int HC = 4 * C;
    constexpr int R = C / 8;           // elements per lane within its head
    int w = (blockIdx.x * blockDim.x + threadIdx.x) >> 5;
    if (w >= n) return;
    int lane = threadIdx.x & 31;
    int hd = lane >> 3, c0 = lane & 7;
    int base = hd * C + c0;

    float attr[R], xrd[R], acc[R];
    const float* xrp = xr + (size_t)w * HC;
    const float* xlp = xl + (size_t)w * HC;
#pragma unroll
    for (int i = 0; i < R; i++) {
        attr[i] = att[base + 8 * i];
        xrd[i] = xrp[base + 8 * i];
    }
    // self-loop edge first (src = dst = w)
    float p = 0.f;
#pragma unroll
    for (int i = 0; i < R; i++) {
        float xv = xlp[base + 8 * i];
        acc[i] = xv;
        float v = xv + xrd[i];
        v = v > 0.f ? v : 0.2f * v;
        p += v * attr[i];
    }
    p += __shfl_xor_sync(0xffffffffu, p, 1);
    p += __shfl_xor_sync(0xffffffffu, p, 2);
    p += __shfl_xor_sync(0xffffffffu, p, 4);
    float m = p, ssum = 1.f;

    int e1 = rowptr[w + 1];
    for (int e = rowptr[w]; e < e1; e++) {
        int s = csrc[e];
        const float* xs = xl + (size_t)s * HC;
        float xv[R];
        float q = 0.f;
#pragma unroll
        for (int i = 0; i < R; i++) {
            xv[i] = xs[base + 8 * i];
            float v = xv[i] + xrd[i];
            v = v > 0.f ? v : 0.2f * v;
            q += v * attr[i];
        }
        q += __shfl_xor_sync(0xffffffffu, q, 1);
        q += __shfl_xor_sync(0xffffffffu, q, 2);
        q += __shfl_xor_sync(0xffffffffu, q, 4);
        float mn = fmaxf(m, q);
        float corr = __expf(m - mn);
        float wq = __expf(q - mn);
        ssum = ssum * corr + wq;
        m = mn;
#pragma unroll
        for (int i = 0; i < R; i++) acc[i] = acc[i] * corr + wq * xv[i];
    }
    float inv = 1.f / ssum;
#pragma unroll
    for (int i = 0; i < R; i++) {
        float t = acc[i] * inv;
        t += __shfl_xor_sync(0xffffffffu, t, 8);
        t += __shfl_xor_sync(0xffffffffu, t, 16);
        if (lane < 8) {
            float v = 0.25f * t + bias[c0 + 8 * i];
            if (elu) v = v > 0.f ? v : expm1f(v);
            out[(size_t)w * C + c0 + 8 * i] = v;
        }
    }
}

// ---------------- JK concat ----------------
__global__ void k_concat(const float* __restrict__ x0, const float* __restrict__ x1,
                         const float* __restrict__ x2, float* __restrict__ cat) {
    int i = blockIdx.x * blockDim.x + threadIdx.x;
    if (i >= NT * 224) return;
    int r = i / 224, j = i - r * 224;
    float v;
    if (j < 128)      v = x0[r * 128 + j];
    else if (j < 192) v = x1[r * 64 + (j - 128)];
    else              v = x2[r * 32 + (j - 192)];
    cat[i] = v;
}

// ---------------- host orchestration ----------------
extern "C" void kernel_launch(void* const* d_in, const int* in_sizes, int n_in,
                              void* d_out, int out_size) {
    const float* mm_f = (const float*)d_in[0];
    const float* d_sf = (const float*)d_in[1];
    const float* ms   = (const float*)d_in[2];
    const float* ds   = (const float*)d_in[3];
    const int*   mme  = (const int*)d_in[4];
    const int*   dde  = (const int*)d_in[5];
    const int*   ei   = (const int*)d_in[6];
    const float* W_m1 = (const float*)d_in[7];
    const float* b_m1 = (const float*)d_in[8];
    const float* W_m2 = (const float*)d_in[9];
    const float* b_m2 = (const float*)d_in[10];
    const float* W_d1 = (const float*)d_in[11];
    const float* b_d1 = (const float*)d_in[12];
    const float* W_d2 = (const float*)d_in[13];
    const float* b_d2 = (const float*)d_in[14];
    const float* Wl1  = (const float*)d_in[15];
    const float* Wr1  = (const float*)d_in[16];
    const float* att1 = (const float*)d_in[17];
    const float* bia1 = (const float*)d_in[18];
    const float* Wl2  = (const float*)d_in[19];
    const float* Wr2  = (const float*)d_in[20];
    const float* att2 = (const float*)d_in[21];
    const float* bia2 = (const float*)d_in[22];
    const float* W_jk = (const float*)d_in[23];
    const float* b_jk = (const float*)d_in[24];

    void* vp;
    float *p_ew, *p_dinv, *p_h, *p_xr, *p_tmp, *p_x0, *p_x1, *p_x2, *p_cat;
    float *p_nrm_mm, *p_nrm_dd;
    int *p_cnt, *p_pos, *p_ptr_mm, *p_src_mm, *p_ptr_dd, *p_src_dd, *p_ptr_g, *p_src_g;
    cudaGetSymbolAddress(&vp, g_ew);     p_ew     = (float*)vp;
    cudaGetSymbolAddress(&vp, g_dinv);   p_dinv   = (float*)vp;
    cudaGetSymbolAddress(&vp, g_h);      p_h      = (float*)vp;
    cudaGetSymbolAddress(&vp, g_xr);     p_xr     = (float*)vp;
    cudaGetSymbolAddress(&vp, g_tmp);    p_tmp    = (float*)vp;
    cudaGetSymbolAddress(&vp, g_x0);     p_x0     = (float*)vp;
    cudaGetSymbolAddress(&vp, g_x1);     p_x1     = (float*)vp;
    cudaGetSymbolAddress(&vp, g_x2);     p_x2     = (float*)vp;
    cudaGetSymbolAddress(&vp, g_cat);    p_cat    = (float*)vp;
    cudaGetSymbolAddress(&vp, g_cnt);    p_cnt    = (int*)vp;
    cudaGetSymbolAddress(&vp, g_pos);    p_pos    = (int*)vp;
    cudaGetSymbolAddress(&vp, g_ptr_mm); p_ptr_mm = (int*)vp;
    cudaGetSymbolAddress(&vp, g_src_mm); p_src_mm = (int*)vp;
    cudaGetSymbolAddress(&vp, g_nrm_mm); p_nrm_mm = (float*)vp;
    cudaGetSymbolAddress(&vp, g_ptr_dd); p_ptr_dd = (int*)vp;
    cudaGetSymbolAddress(&vp, g_src_dd); p_src_dd = (int*)vp;
    cudaGetSymbolAddress(&vp, g_nrm_dd); p_nrm_dd = (float*)vp;
    cudaGetSymbolAddress(&vp, g_ptr_g);  p_ptr_g  = (int*)vp;
    cudaGetSymbolAddress(&vp, g_src_g);  p_src_g  = (int*)vp;

    // ---- full GCN branch (CSR build + 2 layers) ----
    auto run_gcn = [&](const float* x, const int* edges, int E, int n, const float* mat,
                       const float* W1, const float* b1, const float* W2, const float* b2,
                       int* ptr, int* csrc, float* cnorm, float* out) {
        const int* src = edges;
        const int* dst = edges + E;
        k_zeroi<<<cdiv(n, 256), 256>>>(p_cnt, n);
        k_gather_hist<<<cdiv(E, 256), 256>>>(mat, src, dst, p_ew, p_pos, p_cnt, E, n);
        k_fill<<<cdiv(n, 256), 256>>>(p_dinv, 1.f, n);
        k_deg_acc<<<cdiv(E, 256), 256>>>(dst, p_ew, p_dinv, E);
        k_rsqrt<<<cdiv(n, 256), 256>>>(p_dinv, n);
        k_scan<<<1, 1024>>>(p_cnt, ptr, n);
        k_scatter_gcn<<<cdiv(E, 256), 256>>>(src, dst, p_ew, p_pos, ptr, p_dinv, csrc, cnorm, E);
        // layer 1
        k_gemm8<<<n / 8, 128>>>(x, W1, nullptr, p_h, 128, 128, 0);
        k_gcn_agg<<<cdiv(n * 32, 256), 256>>>(ptr, csrc, cnorm, p_h, p_dinv, b1, p_tmp, n, 0);
        // layer 2 (relu on input inside gemm, relu on output fused)
        k_gemm8<<<n / 8, 128>>>(p_tmp, W2, nullptr, p_h, 128, 128, 1);
        k_gcn_agg<<<cdiv(n * 32, 256), 256>>>(ptr, csrc, cnorm, p_h, p_dinv, b2, out, n, 1);
    };
    run_gcn(mm_f, mme, EMM, NM, ms, W_m1, b_m1, W_m2, b_m2,
            p_ptr_mm, p_src_mm, p_nrm_mm, p_x0);
    run_gcn(d_sf, dde, EDD, ND, ds, W_d1, b_d1, W_d2, b_d2,
            p_ptr_dd, p_src_dd, p_nrm_dd, p_x0 + (size_t)NM * 128);

    // ---- GAT graph CSR (built once, used by both layers) ----
    k_zeroi<<<cdiv(NT, 256), 256>>>(p_cnt, NT);
    k_hist<<<cdiv(EG, 256), 256>>>(ei + EG, p_pos, p_cnt, EG);
    k_scan<<<1, 1024>>>(p_cnt, p_ptr_g, NT);
    k_scatter_gat<<<cdiv(EG, 256), 256>>>(ei, ei + EG, p_pos, p_ptr_g, p_src_g, EG);

    // ---- GATv2 layer 1: 128 -> 4x64, elu ----
    k_gemm8_dual<<<NT / 8, 256>>>(p_x0, Wl1, Wr1, p_h, p_xr, 128, 256);
    k_gat_fused<64><<<cdiv(NT * 32, 256), 256>>>(p_ptr_g, p_src_g, p_h, p_xr,
                                                 att1, bia1, p_x1, NT, 1);
    // ---- GATv2 layer 2: 64 -> 4x32 ----
    k_gemm8_dual<<<NT / 8, 128>>>(p_x1, Wl2, Wr2, p_h, p_xr, 64, 128);
    k_gat_fused<32><<<cdiv(NT * 32, 256), 256>>>(p_ptr_g, p_src_g, p_h, p_xr,
                                                 att2, bia2, p_x2, NT, 0);

    // ---- JumpingKnowledge concat + linear ----
    k_concat<<<cdiv(NT * 224, 256), 256>>>(p_x0, p_x1, p_x2, p_cat);
    k_gemm8<<<NT / 8, 128>>>(p_cat, W_jk, b_jk, (float*)d_out, 224, 128, 0);
}